// round 3
// baseline (speedup 1.0000x reference)
#include <cuda_runtime.h>
#include <math.h>

// Shapes fixed by the reference setup_inputs():
//   B=64, S=256, H=768, D=64, NEG=4
// Inputs (metadata order): encoded[B,S,H] f32, n_encoded[B*NEG,S,H] f32,
//   mask1[B,S,1], mask2[B,S,1], mask_u_neg[B*NEG,S,1], W[D,H]
// Output: scalar float loss.

#define PB_EPS 1e-15f
#define PB_BND (1.0f - 1e-7f)

static const int PB_B   = 64;
static const int PB_S   = 256;
static const int PB_H   = 768;
static const int PB_D   = 64;
static const int PB_NEG = 4;
static const int PB_NROWS = PB_B * 2 + PB_B * PB_NEG;   // 384

// Scratch for the 384 projected+mobius-matvec'd vectors:
// rows [0,64)   = u   (mask1 selection)
// rows [64,128) = v   (mask2 selection)
// rows [128,384)= u_neg (b*NEG + k ordering, matching reshape(B,NEG,D))
__device__ float g_vec[PB_NROWS * PB_D];

__device__ __forceinline__ float warp_sum(float v) {
#pragma unroll
    for (int o = 16; o; o >>= 1) v += __shfl_xor_sync(0xffffffffu, v, o);
    return v;
}

// -------------------------------------------------------------------------
// Kernel A: per selected token row
//   x = gather(encoded, one-hot pos)                [H]
//   y = expmap0(x) = tanh(||x||) * x / max(||x||,EPS)
//   mx = W @ y                                      [D]
//   out = tanh(mn/xn * artanh(clip(xn,BND))) * mx / mn
//     xn = max(||y||, EPS), mn = max(||mx||, EPS)
// -------------------------------------------------------------------------
__global__ __launch_bounds__(256, 4)
void pb_rowproj_kernel(const float* __restrict__ encoded,
                       const float* __restrict__ n_encoded,
                       const float* __restrict__ mask1,
                       const float* __restrict__ mask2,
                       const float* __restrict__ mask_neg,
                       const float* __restrict__ W)
{
    const int r    = blockIdx.x;
    const int tid  = threadIdx.x;
    const int wid  = tid >> 5;
    const int lane = tid & 31;

    __shared__ int   s_pos;
    __shared__ float xs[PB_H];       // raw gathered x
    __shared__ float s_red[8];
    __shared__ float mxs[PB_D];
    __shared__ float s_scale;        // tanh(n)/n
    __shared__ float s_xn;           // clip(||y||, EPS)
    __shared__ float s_fac;          // tanh(mn/xn*artanh(xn)) / mn

    const float* mask;
    const float* base;
    if (r < PB_B) {
        mask = mask1 + (size_t)r * PB_S;
        base = encoded + (size_t)r * PB_S * PB_H;
    } else if (r < 2 * PB_B) {
        mask = mask2 + (size_t)(r - PB_B) * PB_S;
        base = encoded + (size_t)(r - PB_B) * PB_S * PB_H;
    } else {
        mask = mask_neg + (size_t)(r - 2 * PB_B) * PB_S;
        base = n_encoded + (size_t)(r - 2 * PB_B) * PB_S * PB_H;
    }

    // one-hot position (exactly one entry == 1.0f)
    if (mask[tid] > 0.5f) s_pos = tid;
    __syncthreads();

    const float* x = base + (size_t)s_pos * PB_H;

    // gather x into smem + sum of squares
    float ss = 0.f;
#pragma unroll
    for (int i = 0; i < PB_H / 256; i++) {
        float v = x[tid + i * 256];
        xs[tid + i * 256] = v;
        ss += v * v;
    }
    ss = warp_sum(ss);
    if (lane == 0) s_red[wid] = ss;
    __syncthreads();
    if (wid == 0) {
        float t = (lane < 8) ? s_red[lane] : 0.f;
        t = warp_sum(t);
        if (lane == 0) {
            float nrm = sqrtf(t);
            float n_cl = fmaxf(nrm, PB_EPS);
            float sc = tanhf(n_cl) / n_cl;     // expmap0 scale
            s_scale = sc;
            s_xn = fmaxf(sc * nrm, PB_EPS);    // ||y|| = scale * ||x||
        }
    }
    __syncthreads();
    const float scale = s_scale;

    // matvec: warp w computes output dims [w*8, w*8+8)
#pragma unroll
    for (int j = 0; j < PB_D / 8; j++) {
        int d = wid * 8 + j;
        const float* wr = W + (size_t)d * PB_H;
        float acc = 0.f;
#pragma unroll
        for (int i = 0; i < PB_H / 32; i++)
            acc = fmaf(wr[lane + i * 32], xs[lane + i * 32], acc);
        acc = warp_sum(acc);
        if (lane == 0) mxs[d] = acc * scale;   // mx = W @ (scale*x)
    }
    __syncthreads();

    // mn and the mobius_matvec rescale factor
    if (wid == 0) {
        float a = mxs[lane];
        float b = mxs[lane + 32];
        float t = warp_sum(a * a + b * b);
        if (lane == 0) {
            float mn = fmaxf(sqrtf(t), PB_EPS);
            float xn = s_xn;
            float ar = atanhf(fminf(xn, PB_BND));
            s_fac = tanhf(mn / xn * ar) / mn;
        }
    }
    __syncthreads();

    if (tid < PB_D)
        g_vec[(size_t)r * PB_D + tid] = s_fac * mxs[tid];
}

// -------------------------------------------------------------------------
// Kernel B: per-batch scalar epilogue (warp per batch), reduce mean into out.
// -------------------------------------------------------------------------
__device__ __forceinline__ float pb_mobius_dist_sq(
    float u0, float u1, float v0, float v1, float x2, float y2, float duv)
{
    // 2 * artanh(|| mobius_add(-u, v) ||)
    float xy = -duv;
    float ca = 1.f + 2.f * xy + y2;   // multiplies (-u)
    float cb = 1.f - x2;              // multiplies v
    float n0 = ca * (-u0) + cb * v0;
    float n1 = ca * (-u1) + cb * v1;
    float nn = warp_sum(n0 * n0 + n1 * n1);
    float den = fmaxf(1.f + 2.f * xy + x2 * y2, PB_EPS);
    float arg = sqrtf(nn) / den;
    return 2.f * atanhf(fminf(arg, PB_BND));
}

__global__ __launch_bounds__(256, 1)
void pb_loss_kernel(float* __restrict__ out)
{
    const int tid  = threadIdx.x;
    const int wid  = tid >> 5;
    const int lane = tid & 31;

    __shared__ float bloss[PB_B];
    __shared__ float s_red[8];

    for (int b = wid; b < PB_B; b += 8) {
        const float* up = g_vec + (size_t)b * PB_D;
        const float* vp = g_vec + (size_t)(PB_B + b) * PB_D;
        const float* np = g_vec + (size_t)(2 * PB_B + b * PB_NEG) * PB_D;

        float u0 = up[lane], u1 = up[lane + 32];
        float v0 = vp[lane], v1 = vp[lane + 32];

        float nu2 = warp_sum(u0 * u0 + u1 * u1);
        float nv2 = warp_sum(v0 * v0 + v1 * v1);
        float duv = warp_sum(u0 * v0 + u1 * v1);
        float d0 = u0 - v0, d1 = u1 - v1;
        float e2 = warp_sum(d0 * d0 + d1 * d1);

        // angle term
        float norm_v = sqrtf(nv2);
        float euclid = sqrtf(e2);
        float rad = fmaxf(1.f + nu2 * nv2 - 2.f * duv, PB_EPS);
        float den = fmaxf(norm_v * euclid * sqrtf(rad), PB_EPS);
        float cosang = (duv * (1.f + nv2) - nv2 * (1.f + nu2)) / den;
        cosang = fminf(fmaxf(cosang, -PB_BND), PB_BND);
        float angle = acosf(cosang);

        // positive-pair distance
        float duvp = pb_mobius_dist_sq(u0, u1, v0, v1, nu2, nv2, duv);
        float e_pos = expf(-duvp);

        // negatives
        float Z1 = 0.f;
#pragma unroll
        for (int k = 0; k < PB_NEG; k++) {
            const float* nk = np + (size_t)k * PB_D;
            float w0 = nk[lane], w1 = nk[lane + 32];
            float y2 = warp_sum(w0 * w0 + w1 * w1);
            float dn = warp_sum(u0 * w0 + u1 * w1);
            float dk = pb_mobius_dist_sq(u0, u1, w0, w1, nu2, y2, dn);
            Z1 += expf(-dk);
        }

        float ns = -logf(e_pos / (Z1 + e_pos));

        // alpha = 0.5: loss_b = 2*(1-a)*angle + 2*a*ns = angle + ns
        if (lane == 0) bloss[b] = angle + ns;
    }
    __syncthreads();

    // mean over 64 batches
    if (wid == 0) {
        float t = bloss[lane] + bloss[lane + 32];
        t = warp_sum(t);
        if (lane == 0) out[0] = t / (float)PB_B;
    }
}

extern "C" void kernel_launch(void* const* d_in, const int* in_sizes, int n_in,
                              void* d_out, int out_size)
{
    const float* encoded   = (const float*)d_in[0];
    const float* n_encoded = (const float*)d_in[1];
    const float* mask1     = (const float*)d_in[2];
    const float* mask2     = (const float*)d_in[3];
    const float* mask_neg  = (const float*)d_in[4];
    const float* W         = (const float*)d_in[5];
    float* out = (float*)d_out;

    pb_rowproj_kernel<<<PB_NROWS, 256>>>(encoded, n_encoded,
                                         mask1, mask2, mask_neg, W);
    pb_loss_kernel<<<1, 256>>>(out);
}

// round 5
// speedup vs baseline: 2.6805x; 2.6805x over previous
#include <cuda_runtime.h>
#include <math.h>

// Shapes fixed by setup_inputs(): B=64, S=256, H=768, D=64, NEG=4
// Inputs: encoded[B,S,H] f32, n_encoded[B*NEG,S,H] f32,
//         mask1[B,S,1], mask2[B,S,1], mask_u_neg[B*NEG,S,1], W[D,H]
// Output: scalar float loss.
//
// Fully fused: one block per batch. Each block projects its 6 token vectors
// (u, v, 4 negatives) through expmap0 + mobius_matvec sharing one pass over W,
// then computes angle + 5 Poincare distances on 6 parallel warps, and
// atomicAdds its per-batch loss/B into out (zeroed via captured memset).

#define PB_EPS 1e-15f
#define PB_BND (1.0f - 1e-7f)

#define PB_B   64
#define PB_S   256
#define PB_H   768
#define PB_D   64
#define PB_NEG 4

__device__ __forceinline__ float warp_sum(float v) {
#pragma unroll
    for (int o = 16; o; o >>= 1) v += __shfl_xor_sync(0xffffffffu, v, o);
    return v;
}

// 2 * artanh(|| mobius_add(-u, w) ||), vectors split 2 elems/lane (D=64).
__device__ __forceinline__ float pb_dist(
    float u0, float u1, float w0, float w1, float x2, float y2, float duw)
{
    float xy  = -duw;
    float ca  = 1.f + 2.f * xy + y2;   // coefficient of (-u)
    float cb  = 1.f - x2;              // coefficient of w
    float n0  = ca * (-u0) + cb * w0;
    float n1  = ca * (-u1) + cb * w1;
    float nn  = warp_sum(n0 * n0 + n1 * n1);
    float den = fmaxf(1.f + 2.f * xy + x2 * y2, PB_EPS);
    float arg = sqrtf(nn) / den;
    return 2.f * atanhf(fminf(arg, PB_BND));
}

__global__ __launch_bounds__(256, 1)
void pb_fused_kernel(const float* __restrict__ encoded,
                     const float* __restrict__ n_encoded,
                     const float* __restrict__ mask1,
                     const float* __restrict__ mask2,
                     const float* __restrict__ mask_neg,
                     const float* __restrict__ W,
                     float* __restrict__ out)
{
    const int b    = blockIdx.x;
    const int tid  = threadIdx.x;
    const int wid  = tid >> 5;
    const int lane = tid & 31;

    __shared__ int   s_pos[6];
    __shared__ float xs[6][PB_H];      // gathered raw token vectors
    __shared__ float s_part[8][6];     // per-warp partial sum-of-squares
    __shared__ float s_scale[6];       // expmap0 scale tanh(n)/n
    __shared__ float s_xn[6];          // clip(||y||, EPS)
    __shared__ float mxs[6][PB_D];     // matvec results -> final vectors (in place)
    __shared__ float s_term[6];        // e_neg0..3, e_pos, angle

    // ---- 1. one-hot position lookup (6 mask rows, S == blockDim) ----
    if (mask1[(size_t)b * PB_S + tid] > 0.5f) s_pos[0] = tid;
    if (mask2[(size_t)b * PB_S + tid] > 0.5f) s_pos[1] = tid;
#pragma unroll
    for (int k = 0; k < PB_NEG; k++)
        if (mask_neg[(size_t)(b * PB_NEG + k) * PB_S + tid] > 0.5f) s_pos[2 + k] = tid;
    __syncthreads();

    // ---- 2. gather 6 rows into smem + sum of squares ----
    const float* xrow[6];
    xrow[0] = encoded + ((size_t)b * PB_S + s_pos[0]) * PB_H;
    xrow[1] = encoded + ((size_t)b * PB_S + s_pos[1]) * PB_H;
#pragma unroll
    for (int k = 0; k < PB_NEG; k++)
        xrow[2 + k] = n_encoded + ((size_t)(b * PB_NEG + k) * PB_S + s_pos[2 + k]) * PB_H;

    float ss[6] = {0.f, 0.f, 0.f, 0.f, 0.f, 0.f};
#pragma unroll
    for (int j = 0; j < 6; j++) {
#pragma unroll
        for (int i = 0; i < PB_H / 256; i++) {
            float v = xrow[j][tid + i * 256];
            xs[j][tid + i * 256] = v;
            ss[j] += v * v;
        }
    }
#pragma unroll
    for (int j = 0; j < 6; j++) ss[j] = warp_sum(ss[j]);
    if (lane == 0) {
#pragma unroll
        for (int j = 0; j < 6; j++) s_part[wid][j] = ss[j];
    }
    __syncthreads();

    // ---- 3. expmap0 scales ----
    if (wid == 0 && lane < 6) {
        float t = 0.f;
#pragma unroll
        for (int w = 0; w < 8; w++) t += s_part[w][lane];
        float nrm  = sqrtf(t);
        float ncl  = fmaxf(nrm, PB_EPS);
        float sc   = tanhf(ncl) / ncl;
        s_scale[lane] = sc;
        s_xn[lane]    = fmaxf(sc * nrm, PB_EPS);  // ||expmap0(x)||, clipped
    }
    __syncthreads();

    // ---- 4. shared matvec: one pass over W serves all 6 vectors ----
    // warp w computes output dims [w*8, w*8+8)
#pragma unroll
    for (int jj = 0; jj < PB_D / 8; jj++) {
        int d = wid * 8 + jj;
        const float* wr = W + (size_t)d * PB_H;
        float a0 = 0.f, a1 = 0.f, a2 = 0.f, a3 = 0.f, a4 = 0.f, a5 = 0.f;
#pragma unroll
        for (int i = 0; i < PB_H / 32; i++) {
            float wv = wr[lane + i * 32];
            int   h  = lane + i * 32;
            a0 = fmaf(wv, xs[0][h], a0);
            a1 = fmaf(wv, xs[1][h], a1);
            a2 = fmaf(wv, xs[2][h], a2);
            a3 = fmaf(wv, xs[3][h], a3);
            a4 = fmaf(wv, xs[4][h], a4);
            a5 = fmaf(wv, xs[5][h], a5);
        }
        a0 = warp_sum(a0); a1 = warp_sum(a1); a2 = warp_sum(a2);
        a3 = warp_sum(a3); a4 = warp_sum(a4); a5 = warp_sum(a5);
        if (lane == 0) {
            mxs[0][d] = a0 * s_scale[0];
            mxs[1][d] = a1 * s_scale[1];
            mxs[2][d] = a2 * s_scale[2];
            mxs[3][d] = a3 * s_scale[3];
            mxs[4][d] = a4 * s_scale[4];
            mxs[5][d] = a5 * s_scale[5];
        }
    }
    __syncthreads();

    // ---- 5. mobius_matvec rescale, in place (6 warps in parallel) ----
    if (wid < 6) {
        float m0 = mxs[wid][lane];
        float m1 = mxs[wid][lane + 32];
        float t  = warp_sum(m0 * m0 + m1 * m1);
        float mn = fmaxf(sqrtf(t), PB_EPS);
        float xn = s_xn[wid];
        float fac = tanhf(mn / xn * atanhf(fminf(xn, PB_BND))) / mn;
        mxs[wid][lane]      = m0 * fac;
        mxs[wid][lane + 32] = m1 * fac;
    }
    __syncthreads();

    // ---- 6. epilogue: 6 warps compute angle + 5 distances in parallel ----
    float u0  = mxs[0][lane];
    float u1  = mxs[0][lane + 32];
    float nu2 = warp_sum(u0 * u0 + u1 * u1);

    if (wid < 4) {                      // negative distances
        float w0 = mxs[2 + wid][lane];
        float w1 = mxs[2 + wid][lane + 32];
        float y2 = warp_sum(w0 * w0 + w1 * w1);
        float dn = warp_sum(u0 * w0 + u1 * w1);
        float dk = pb_dist(u0, u1, w0, w1, nu2, y2, dn);
        if (lane == 0) s_term[wid] = expf(-dk);
    } else if (wid == 4) {              // positive-pair distance
        float v0  = mxs[1][lane];
        float v1  = mxs[1][lane + 32];
        float nv2 = warp_sum(v0 * v0 + v1 * v1);
        float duv = warp_sum(u0 * v0 + u1 * v1);
        float dp  = pb_dist(u0, u1, v0, v1, nu2, nv2, duv);
        if (lane == 0) s_term[4] = expf(-dp);
    } else if (wid == 5) {              // angle term
        float v0  = mxs[1][lane];
        float v1  = mxs[1][lane + 32];
        float nv2 = warp_sum(v0 * v0 + v1 * v1);
        float duv = warp_sum(u0 * v0 + u1 * v1);
        float d0  = u0 - v0, d1 = u1 - v1;
        float e2  = warp_sum(d0 * d0 + d1 * d1);
        float norm_v = sqrtf(nv2);
        float euclid = sqrtf(e2);
        float rad = fmaxf(1.f + nu2 * nv2 - 2.f * duv, PB_EPS);
        float den = fmaxf(norm_v * euclid * sqrtf(rad), PB_EPS);
        float ca  = (duv * (1.f + nv2) - nv2 * (1.f + nu2)) / den;
        ca = fminf(fmaxf(ca, -PB_BND), PB_BND);
        if (lane == 0) s_term[5] = acosf(ca);
    }
    __syncthreads();

    // ---- 7. combine + accumulate mean (alpha=0.5 => weights are 1) ----
    if (tid == 0) {
        float Z1 = s_term[0] + s_term[1] + s_term[2] + s_term[3];
        float ep = s_term[4];
        float ns = -logf(ep / (Z1 + ep));
        atomicAdd(out, (s_term[5] + ns) * (1.0f / PB_B));
    }
}

extern "C" void kernel_launch(void* const* d_in, const int* in_sizes, int n_in,
                              void* d_out, int out_size)
{
    const float* encoded   = (const float*)d_in[0];
    const float* n_encoded = (const float*)d_in[1];
    const float* mask1     = (const float*)d_in[2];
    const float* mask2     = (const float*)d_in[3];
    const float* mask_neg  = (const float*)d_in[4];
    const float* W         = (const float*)d_in[5];
    float* out = (float*)d_out;

    cudaMemsetAsync(out, 0, sizeof(float));
    pb_fused_kernel<<<PB_B, 256>>>(encoded, n_encoded,
                                   mask1, mask2, mask_neg, W, out);
}